// round 10
// baseline (speedup 1.0000x reference)
#include <cuda_runtime.h>

#define DIM     1024
#define NPAIRS  512
#define NLAYER  10
#define NACTIVE 2044   // params for layers 1..9: 2*sum(DIM>>l, l=1..9)
#define CTAS    740    // 5 CTAs/SM * 148 SMs — exactly one persistent wave

// Single persistent kernel.
//
// Math: with base point 0 both Mobius maps are radial scalings
//   log0(x) = atanh(|x|)/|x| x,  exp0(v) = tanh(|v|)/|v| v,
// and the butterfly always pairs adjacent elements (2k,2k+1), acting as
// [[a,b],[-b,a]] = complex multiply by (a - ib). The whole stack is one
// complex W_k per pair (512 values), and
//   |butterfly(u)|^2 = s1^2 * sum_k |W_k|^2 (x_{2k}^2 + x_{2k+1}^2).
//
// R9 fix: __launch_bounds__(256, 5) — R9's build let ptxas use 80 regs
// (occ 30%, two waves, DVFS-sensitive). Cap at 48 regs like the proven R8
// body so 740 CTAs fit in ONE wave at 5 CTAs/SM.
__global__ void __launch_bounds__(256, 5)
hyper_butterfly_persistent(const float* __restrict__ x,
                           const float* __restrict__ params,
                           float* __restrict__ out,
                           int rows) {
    __shared__ float sp[NACTIVE];                  // 8 KB raw params (layers 1..9)
    __shared__ __align__(16) float2 sW[NPAIRS];    // 4 KB composite coefficients

    const int t    = threadIdx.x;
    const int warp = t >> 5;
    const int lane = t & 31;

    // ── Prologue A: coalesced batch-load of active params (one round trip).
#pragma unroll
    for (int j = 0; j < 8; ++j) {
        int i = t + 256 * j;
        if (i < NACTIVE) sp[i] = params[2 * DIM + i];
    }
    __syncthreads();

    // ── Prologue B: compose W per pair; thread t does pairs t and t+256.
#pragma unroll
    for (int h = 0; h < 2; ++h) {
        const int k = t + h * 256;
        float A = 1.0f, B = 0.0f;
        int off = 0;
#pragma unroll
        for (int l = 1; l < NLAYER; ++l) {
            const int blk = k >> (l - 1);
            const float a = sp[off + 2 * blk];
            const float b = sp[off + 2 * blk + 1];
            const float nA = A * a + B * b;        // (A+iB)*(a-ib)
            const float nB = B * a - A * b;
            A = nA; B = nB;
            off += 2 * (DIM >> l);
        }
        sW[k] = make_float2(A, B);
    }
    __syncthreads();

    const float4* __restrict__ sW4 = reinterpret_cast<const float4*>(sW);
    const int stride = gridDim.x << 3;             // total warps

    // ── Persistent row loop: warp-per-row, shuffle-only reduction,
    //    W served from smem (conflict-free LDS.128).
    for (int row = (blockIdx.x << 3) + warp; row < rows; row += stride) {
        const float4* __restrict__ xr = reinterpret_cast<const float4*>(x + (size_t)row * DIM);
        float4* __restrict__ orow     = reinterpret_cast<float4*>(out + (size_t)row * DIM);

        // Front-batched loads (MLP=8); norm partials.
        float4 xv[8];
#pragma unroll
        for (int j = 0; j < 8; ++j) xv[j] = xr[lane + 32 * j];

        float r0 = 0.0f, r1 = 0.0f;
#pragma unroll
        for (int j = 0; j < 8; ++j) {
            const float4 w = sW4[lane + 32 * j];
            const float q0 = xv[j].x * xv[j].x + xv[j].y * xv[j].y;
            const float q1 = xv[j].z * xv[j].z + xv[j].w * xv[j].w;
            r0 += q0 + q1;
            r1 += (w.x * w.x + w.y * w.y) * q0
                + (w.z * w.z + w.w * w.w) * q1;
        }

        // Warp butterfly reduce both sums; every lane gets the totals.
#pragma unroll
        for (int o = 16; o; o >>= 1) {
            r0 += __shfl_xor_sync(0xffffffffu, r0, o);
            r1 += __shfl_xor_sync(0xffffffffu, r1, o);
        }

        const float n  = sqrtf(r0);
        const float s1 = atanhf(n) / fmaxf(n, 1e-12f);
        const float m  = s1 * sqrtf(r1);
        const float s  = s1 * tanhf(m) / fmaxf(m, 1e-12f);

        // Rotate, scale, store.
#pragma unroll
        for (int j = 0; j < 8; ++j) {
            const float4 w = sW4[lane + 32 * j];
            float4 o4;
            o4.x = s * (w.x * xv[j].x - w.y * xv[j].y);
            o4.y = s * (w.x * xv[j].y + w.y * xv[j].x);
            o4.z = s * (w.z * xv[j].z - w.w * xv[j].w);
            o4.w = s * (w.z * xv[j].w + w.w * xv[j].z);
            orow[lane + 32 * j] = o4;
        }
    }
}

extern "C" void kernel_launch(void* const* d_in, const int* in_sizes, int n_in,
                              void* d_out, int out_size) {
    const float* x      = (const float*)d_in[0];
    const float* params = (const float*)d_in[1];
    float* out          = (float*)d_out;

    const int rows = in_sizes[0] / DIM;   // 32768
    hyper_butterfly_persistent<<<CTAS, 256>>>(x, params, out, rows);
}

// round 11
// speedup vs baseline: 1.4605x; 1.4605x over previous
#include <cuda_runtime.h>

#define DIM     1024
#define NPAIRS  512
#define NLAYER  10
#define NACTIVE 2044   // params for layers 1..9: 2*sum(DIM>>l, l=1..9)

// Single kernel, grid = rows/8, 8 rows per CTA (warp-per-row).
//
// Math: with base point 0 both Mobius maps are radial scalings
//   log0(x) = atanh(|x|)/|x| x,  exp0(v) = tanh(|v|)/|v| v,
// and the butterfly always pairs adjacent elements (2k,2k+1), acting as
// [[a,b],[-b,a]] = complex multiply by (a - ib): one composite W_k per pair,
//   |butterfly(u)|^2 = s1^2 * sum_k |W_k|^2 (x_{2k}^2 + x_{2k+1}^2).
//
// Register-pressure fix (R9 blew to 80 regs, R10's 48-cap spilled): the row is
// processed in TWO passes so no xv[8] array is ever live across the reduction.
// Pass 2 re-reads x from L1/L2 (row just touched, 4KB/warp); a memory clobber
// between passes prevents ptxas from CSE-ing the reload into registers.
//
// Per-CTA W build: params are BATCH-loaded coalesced into smem (one round
// trip; L2-hot after wave 1), then the 9-layer chain walks smem — not the
// dependent global chain that sank the R5 fused kernel. The 8KB smem buffer
// is reused: raw params first, then W table (4KB) + |W|^2 table (2KB).
__global__ void __launch_bounds__(256, 4)
hyper_butterfly_2pass(const float* __restrict__ x,
                      const float* __restrict__ params,
                      float* __restrict__ out) {
    __shared__ __align__(16) float buf[2048];      // 8 KB, reused

    const int t    = threadIdx.x;
    const int warp = t >> 5;
    const int lane = t & 31;

    // ── Prologue A: coalesced batch-load of active params.
#pragma unroll
    for (int j = 0; j < 8; ++j) {
        int i = t + 256 * j;
        if (i < NACTIVE) buf[i] = params[2 * DIM + i];
    }
    __syncthreads();

    // ── Prologue B: compose W for pairs t and t+256, keep in registers.
    float A[2], B[2];
#pragma unroll
    for (int h = 0; h < 2; ++h) {
        const int k = t + h * 256;
        float a0 = 1.0f, b0 = 0.0f;
        int off = 0;
#pragma unroll
        for (int l = 1; l < NLAYER; ++l) {
            const int blk = k >> (l - 1);
            const float a = buf[off + 2 * blk];
            const float b = buf[off + 2 * blk + 1];
            const float na = a0 * a + b0 * b;      // (a0+ib0)*(a-ib)
            const float nb = b0 * a - a0 * b;
            a0 = na; b0 = nb;
            off += 2 * (DIM >> l);
        }
        A[h] = a0; B[h] = b0;
    }
    __syncthreads();   // all param reads done before buffer reuse

    // ── Prologue C: write W tables into the reused buffer.
    //   buf[0..1023]    = float2 W_k (as float4 per 2-pair chunk)
    //   buf[1024..1535] = |W_k|^2 (as float2 per chunk)
#pragma unroll
    for (int h = 0; h < 2; ++h) {
        const int k = t + h * 256;
        reinterpret_cast<float2*>(buf)[k] = make_float2(A[h], B[h]);
        buf[1024 + k] = A[h] * A[h] + B[h] * B[h];
    }
    __syncthreads();

    const float4* __restrict__ sW4 = reinterpret_cast<const float4*>(buf);
    const float2* __restrict__ sZ  = reinterpret_cast<const float2*>(buf + 1024);

    const int row = (blockIdx.x << 3) + warp;
    const float4* __restrict__ xr = reinterpret_cast<const float4*>(x + (size_t)row * DIM);
    float4* __restrict__ orow     = reinterpret_cast<float4*>(out + (size_t)row * DIM);

    // ── Pass 1: stream x, accumulate both norms. No persistent x registers.
    float r0 = 0.0f, r1 = 0.0f;
#pragma unroll
    for (int j = 0; j < 8; ++j) {
        const float4 xv = xr[lane + 32 * j];
        const float2 wz = sZ[lane + 32 * j];
        const float q0 = xv.x * xv.x + xv.y * xv.y;
        const float q1 = xv.z * xv.z + xv.w * xv.w;
        r0 += q0 + q1;
        r1 += wz.x * q0 + wz.y * q1;
    }

    // Warp butterfly reduce both sums; every lane gets the totals.
#pragma unroll
    for (int o = 16; o; o >>= 1) {
        r0 += __shfl_xor_sync(0xffffffffu, r0, o);
        r1 += __shfl_xor_sync(0xffffffffu, r1, o);
    }

    const float n  = sqrtf(r0);
    const float s1 = atanhf(n) / fmaxf(n, 1e-12f);
    const float m  = s1 * sqrtf(r1);
    const float s  = s1 * tanhf(m) / fmaxf(m, 1e-12f);

    // Force pass 2 to genuinely reload x (L1/L2 hit) instead of keeping
    // 32 registers of x live across the reduction.
    asm volatile("" ::: "memory");

    // ── Pass 2: reload, rotate, scale, store.
#pragma unroll
    for (int j = 0; j < 8; ++j) {
        const float4 xv = xr[lane + 32 * j];
        const float4 w  = sW4[lane + 32 * j];
        float4 o4;
        o4.x = s * (w.x * xv.x - w.y * xv.y);
        o4.y = s * (w.x * xv.y + w.y * xv.x);
        o4.z = s * (w.z * xv.z - w.w * xv.w);
        o4.w = s * (w.z * xv.w + w.w * xv.z);
        orow[lane + 32 * j] = o4;
    }
}

extern "C" void kernel_launch(void* const* d_in, const int* in_sizes, int n_in,
                              void* d_out, int out_size) {
    const float* x      = (const float*)d_in[0];
    const float* params = (const float*)d_in[1];
    float* out          = (float*)d_out;

    const int rows = in_sizes[0] / DIM;   // 32768
    hyper_butterfly_2pass<<<rows >> 3, 256>>>(x, params, out);
}